// round 14
// baseline (speedup 1.0000x reference)
#include <cuda_runtime.h>
#include <cstdint>
#include <cfloat>
#include <math.h>

#define Bb 32
#define Nn 64
#define Mm 64
#define Cc 64
#define C1d 16
#define Hh 256
#define TH 768
#define FD 912
#define GD 2992

// ---------------- device scratch ----------------
__device__ float  s_P[(size_t)Bb * Nn * Mm * TH];   // input proj of every states row [131072][768]
__device__ float  s_F[(size_t)Bb * Nn * FD];        // f [2048][912]
__device__ float  s_XW1[(size_t)Bb * Nn * TH];      // gru1d input proj [2048][768]
__device__ float4 s_Wrz[(size_t)Hh * Hh];           // [k][j] = (wr,wr,wz,wz) duplicated
__device__ float2 s_Wn [(size_t)Hh * Hh];           // [k][j] = (wn,wn)
__device__ float  s_Whh1T[Hh * TH];                 // [256][768]
__device__ float  s_fc1Wt[GD * Hh];                 // [2992][256]
__device__ float  s_G[Bb * GD];
__device__ float  s_H2[Bb * Hh];
__device__ int    s_perm1[Nn * Mm];
__device__ int    s_perm2[Nn * Nn];

// ---------------- helpers ----------------
__device__ __forceinline__ float2 upk2(unsigned long long v) {
    float2 r;
    asm("mov.b64 {%0, %1}, %2;" : "=f"(r.x), "=f"(r.y) : "l"(v));
    return r;
}
__device__ __forceinline__ unsigned long long pk2(float lo, float hi) {
    unsigned long long r;
    asm("mov.b64 %0, {%1, %2};" : "=l"(r) : "f"(lo), "f"(hi));
    return r;
}
__device__ __forceinline__ void fma2p(unsigned long long& d, unsigned long long a, unsigned long long b) {
    asm("fma.rn.f32x2 %0, %1, %2, %0;" : "+l"(d) : "l"(a), "l"(b));
}
__device__ __forceinline__ float th_fast(float x) {
    float y; asm("tanh.approx.f32 %0, %1;" : "=f"(y) : "f"(x)); return y;
}
__device__ __forceinline__ float sg_fast(float x) {
    return fmaf(th_fast(x * 0.5f), 0.5f, 0.5f);
}
__device__ __forceinline__ void cpa16(uint32_t dst, const void* src) {
    asm volatile("cp.async.cg.shared.global [%0], [%1], 16;" :: "r"(dst), "l"(src));
}

// ---------------- both perm conversions (int64 vs int32 detect) ----------------
__global__ void perm_conv_v13(const int* __restrict__ r1, const int* __restrict__ r2) {
    const int* raw = blockIdx.x ? r2 : r1;
    int* out = blockIdx.x ? s_perm2 : s_perm1;
    const int n = Nn * Mm;   // 4096 both
    __shared__ int notI64;
    if (threadIdx.x == 0) notI64 = 0;
    __syncthreads();
    for (int i = threadIdx.x; i < n / 2; i += blockDim.x)
        if (raw[2 * i + 1] != 0) notI64 = 1;
    __syncthreads();
    if (notI64) { for (int i = threadIdx.x; i < n; i += blockDim.x) out[i] = raw[i]; }
    else        { for (int i = threadIdx.x; i < n; i += blockDim.x) out[i] = raw[2 * i]; }
}

// ---------------- transpose in[R][C] -> out[C][R] ----------------
__global__ void tr_v13(const float* __restrict__ in, float* __restrict__ out, int R, int C) {
    int idx = blockIdx.x * 256 + threadIdx.x;
    if (idx < R * C) { int r = idx / C, c = idx % C; out[c * R + r] = in[idx]; }
}

// ---------------- gru2d weight prep: transpose + gate-pack + duplicate ----------------
__global__ void wpack_v13(const float* __restrict__ in) {
    int idx = blockIdx.x * 256 + threadIdx.x;     // 65536 total
    if (idx < Hh * Hh) {
        int k = idx >> 8, j = idx & 255;
        float wr = in[(size_t)j * Hh + k];
        float wz = in[(size_t)(Hh + j) * Hh + k];
        float wn = in[(size_t)(2 * Hh + j) * Hh + k];
        s_Wrz[(size_t)k * Hh + j] = make_float4(wr, wr, wz, wz);
        s_Wn [(size_t)k * Hh + j] = make_float2(wn, wn);
    }
}

// ---------------- stats over states + x1 copy -> F[:, 0:400] ----------------
__global__ void stats_v13(const float* __restrict__ states, const float* __restrict__ x1) {
    int bi = blockIdx.x;               // b*64 + i
    int b = bi >> 6, i = bi & 63;
    int c = threadIdx.x;               // 64 threads
    float* fr = s_F + (size_t)bi * FD;

    float mx = -FLT_MAX, mn = FLT_MAX, sm = 0.0f;
    for (int n = 0; n < Nn; ++n) {
        float v = states[(((size_t)(b * Nn + n)) * Mm + i) * Cc + c];
        mx = fmaxf(mx, v); mn = fminf(mn, v); sm += v;
    }
    fr[C1d + c]          = mx;
    fr[C1d + Cc + c]     = sm * (1.0f / 64.0f);
    fr[C1d + 2 * Cc + c] = mn;

    mx = -FLT_MAX; mn = FLT_MAX; sm = 0.0f;
    for (int m = 0; m < Mm; ++m) {
        float v = states[(((size_t)(b * Nn + i)) * Mm + m) * Cc + c];
        mx = fmaxf(mx, v); mn = fminf(mn, v); sm += v;
    }
    fr[C1d + 3 * Cc + c] = mx;
    fr[C1d + 4 * Cc + c] = sm * (1.0f / 64.0f);
    fr[C1d + 5 * Cc + c] = mn;

    if (c < C1d) fr[c] = x1[bi * C1d + c];
}

// ---------------- SGEMM 128x64 tile: C[M][N] = A[M][K] @ B[N][K]^T + bias[N] ----------------
__global__ void mm128_v13(const float* __restrict__ A, const float* __restrict__ Bm,
                          const float* __restrict__ bias, float* __restrict__ Cm,
                          int K, int Ndim) {
    __shared__ __align__(16) float As[16][132];
    __shared__ __align__(16) float Bs[16][68];
    const int tx = threadIdx.x, ty = threadIdx.y;
    const int tid = ty * 16 + tx;
    const int m0 = blockIdx.y * 128, n0 = blockIdx.x * 64;

    float acc[8][4];
    #pragma unroll
    for (int i = 0; i < 8; ++i)
        #pragma unroll
        for (int jj = 0; jj < 4; ++jj) acc[i][jj] = 0.0f;

    for (int k0 = 0; k0 < K; k0 += 16) {
        #pragma unroll
        for (int e = 0; e < 8; ++e) {
            int idx = tid + e * 256;
            int r = idx >> 4, kk = idx & 15;
            As[kk][r] = A[(size_t)(m0 + r) * K + k0 + kk];
        }
        #pragma unroll
        for (int e = 0; e < 4; ++e) {
            int idx = tid + e * 256;
            int r = idx >> 4, kk = idx & 15;
            Bs[kk][r] = Bm[(size_t)(n0 + r) * K + k0 + kk];
        }
        __syncthreads();
        #pragma unroll
        for (int kk = 0; kk < 16; ++kk) {
            float4 a0 = *reinterpret_cast<const float4*>(&As[kk][ty * 8]);
            float4 a1 = *reinterpret_cast<const float4*>(&As[kk][ty * 8 + 4]);
            float4 b4 = *reinterpret_cast<const float4*>(&Bs[kk][tx * 4]);
            float av[8] = {a0.x, a0.y, a0.z, a0.w, a1.x, a1.y, a1.z, a1.w};
            float bv[4] = {b4.x, b4.y, b4.z, b4.w};
            #pragma unroll
            for (int i = 0; i < 8; ++i)
                #pragma unroll
                for (int jj = 0; jj < 4; ++jj)
                    acc[i][jj] = fmaf(av[i], bv[jj], acc[i][jj]);
        }
        __syncthreads();
    }
    float4 bia = *reinterpret_cast<const float4*>(&bias[n0 + tx * 4]);
    #pragma unroll
    for (int i = 0; i < 8; ++i) {
        float4 v = make_float4(acc[i][0] + bia.x, acc[i][1] + bia.y,
                               acc[i][2] + bia.z, acc[i][3] + bia.w);
        *reinterpret_cast<float4*>(&Cm[(size_t)(m0 + ty * 8 + i) * Ndim + n0 + tx * 4]) = v;
    }
}

// ---------------- persistent 2D GRU: G=32 seqs/CTA, 256 threads, packed-dup weights ----------------
// smem: h[256][36] + xw[32][768] + rows[32][64] = 143360 B
__global__ void __launch_bounds__(256)
rnn2d_v13(const float* __restrict__ bhh) {
    const int dir  = blockIdx.x >> 6;           // 0: sd1, 1: sd2
    const int seq0 = (blockIdx.x & 63) * 32;
    const int j    = threadIdx.x;

    extern __shared__ __align__(16) float dyn[];
    float (*sh_h)[36] = (float (*)[36])dyn;              // [256][36]
    float* sh_xw  = dyn + 256 * 36;                      // [32][768]
    int*   sh_row = (int*)(dyn + 256 * 36 + 32 * TH);    // [32][64]

    #pragma unroll
    for (int g = 0; g < 36; ++g) sh_h[j][g] = 0.0f;

    for (int e = j; e < 32 * 64; e += 256) {
        int g = e >> 6, t = e & 63;
        int s = seq0 + g;
        int b = s >> 6, n = s & 63;
        sh_row[e] = (dir == 0)
            ? (b * Nn + n) * Mm + s_perm1[n * Mm + t]
            : (b * Nn + s_perm2[n * Nn + t]) * Mm + n;
    }

    const unsigned long long bR2 = pk2(bhh[j], bhh[j]);
    const unsigned long long bZ2 = pk2(bhh[Hh + j], bhh[Hh + j]);
    const unsigned long long bN2 = pk2(bhh[2 * Hh + j], bhh[2 * Hh + j]);

    const int my_g = j >> 3;                    // 32 rows, 8 threads per row
    const int my_c = j & 7;
    uint32_t xw_dst = (uint32_t)__cvta_generic_to_shared(sh_xw + my_g * TH);
    __syncthreads();

    for (int t = 0; t < 64; ++t) {
        // async-gather the 32 precomputed xw rows (32 x 3KB) into smem
        const float* src_row = s_P + (size_t)sh_row[my_g * 64 + t] * TH;
        #pragma unroll
        for (int i = 0; i < 24; ++i) {
            int c16 = my_c + 8 * i;
            cpa16(xw_dst + c16 * 16, src_row + c16 * 4);
        }
        asm volatile("cp.async.commit_group;");

        // ----- recurrent matvec for 16 lane-pairs (32 seqs) -----
        unsigned long long accR[16], accZ[16], ghN[16];
        #pragma unroll
        for (int g = 0; g < 16; ++g) { accR[g] = bR2; accZ[g] = bZ2; ghN[g] = bN2; }

        const float4* wrzp = s_Wrz + j;
        const float2* wnp  = s_Wn + j;
        #pragma unroll 4
        for (int k = 0; k < Hh; ++k) {
            float4 wrz = wrzp[(size_t)k * Hh];       // (wr,wr,wz,wz) — LDG.128
            float2 wnn = wnp[(size_t)k * Hh];        // (wn,wn)       — LDG.64
            unsigned long long wr2 = reinterpret_cast<const unsigned long long*>(&wrz)[0];
            unsigned long long wz2 = reinterpret_cast<const unsigned long long*>(&wrz)[1];
            unsigned long long wn2 = *reinterpret_cast<const unsigned long long*>(&wnn);
            const ulonglong2* hrow = reinterpret_cast<const ulonglong2*>(&sh_h[k][0]);
            #pragma unroll
            for (int q = 0; q < 8; ++q) {
                ulonglong2 hp = hrow[q];             // pairs 2q, 2q+1
                fma2p(accR[2 * q],     wr2, hp.x);
                fma2p(accZ[2 * q],     wz2, hp.x);
                fma2p(ghN[2 * q],      wn2, hp.x);
                fma2p(accR[2 * q + 1], wr2, hp.y);
                fma2p(accZ[2 * q + 1], wz2, hp.y);
                fma2p(ghN[2 * q + 1],  wn2, hp.y);
            }
        }

        asm volatile("cp.async.wait_group 0;" ::: "memory");
        __syncthreads();

        float hnew[32];
        #pragma unroll
        for (int gg = 0; gg < 16; ++gg) {
            const float* x0 = sh_xw + (2 * gg) * TH + j;
            const float* x1 = sh_xw + (2 * gg + 1) * TH + j;
            float2 aR = upk2(accR[gg]);
            float2 aZ = upk2(accZ[gg]);
            float2 hN = upk2(ghN[gg]);
            float r0 = sg_fast(aR.x + x0[0]);
            float z0 = sg_fast(aZ.x + x0[Hh]);
            float n0 = th_fast(x0[2 * Hh] + r0 * hN.x);
            hnew[2 * gg]     = (1.0f - z0) * n0 + z0 * sh_h[j][2 * gg];
            float r1 = sg_fast(aR.y + x1[0]);
            float z1 = sg_fast(aZ.y + x1[Hh]);
            float n1 = th_fast(x1[2 * Hh] + r1 * hN.y);
            hnew[2 * gg + 1] = (1.0f - z1) * n1 + z1 * sh_h[j][2 * gg + 1];
        }
        __syncthreads();
        #pragma unroll
        for (int g = 0; g < 32; ++g) sh_h[j][g] = hnew[g];
        __syncthreads();
    }

    const int off = (dir == 0) ? (C1d + 6 * Cc) : (C1d + 6 * Cc + Hh);  // 400 / 656
    #pragma unroll
    for (int g = 0; g < 32; ++g)
        s_F[(size_t)(seq0 + g) * FD + off + j] = sh_h[j][g];
}

// ---------------- 1D GRU: 32 blocks x 256 threads, float4 weight rows ----------------
__global__ void rnn1d_v13(const float* __restrict__ bhh) {
    const int b = blockIdx.x;
    const int tid = threadIdx.x;
    __shared__ float sh_h[Hh];
    __shared__ float sums[TH];
    sh_h[tid] = 0.0f;
    const float br = bhh[tid], bz = bhh[Hh + tid], bn = bhh[2 * Hh + tid];
    __syncthreads();

    for (int t = 0; t < 64; ++t) {
        if (tid < 192) {
            float4 acc = make_float4(0.0f, 0.0f, 0.0f, 0.0f);
            const float* wbase = s_Whh1T + 4 * tid;
            #pragma unroll 8
            for (int k = 0; k < Hh; ++k) {
                float4 w = *reinterpret_cast<const float4*>(wbase + k * TH);
                float hv = sh_h[k];
                acc.x = fmaf(w.x, hv, acc.x);
                acc.y = fmaf(w.y, hv, acc.y);
                acc.z = fmaf(w.z, hv, acc.z);
                acc.w = fmaf(w.w, hv, acc.w);
            }
            *reinterpret_cast<float4*>(&sums[4 * tid]) = acc;
        }
        __syncthreads();

        const float* xw = s_XW1 + (size_t)(b * 64 + t) * TH;  // includes bih
        float r = sg_fast(xw[tid] + sums[tid] + br);
        float z = sg_fast(xw[Hh + tid] + sums[Hh + tid] + bz);
        float n = th_fast(xw[2 * Hh + tid] + r * (sums[2 * Hh + tid] + bn));
        float hnew = (1.0f - z) * n + z * sh_h[tid];
        __syncthreads();
        sh_h[tid] = hnew;
        __syncthreads();
    }
    s_G[(size_t)b * GD + 3 * FD + tid] = sh_h[tid];
}

// ---------------- g = [f.max(1), f.mean(1), f.min(1)] -> G[:, 0:2736] ----------------
__global__ void gpool_v13() {
    const int b = blockIdx.x;
    for (int c = threadIdx.x; c < FD; c += 256) {
        float mx = -FLT_MAX, mn = FLT_MAX, sm = 0.0f;
        for (int n = 0; n < Nn; ++n) {
            float v = s_F[(size_t)(b * Nn + n) * FD + c];
            mx = fmaxf(mx, v); mn = fminf(mn, v); sm += v;
        }
        s_G[(size_t)b * GD + c]          = mx;
        s_G[(size_t)b * GD + FD + c]     = sm * (1.0f / 64.0f);
        s_G[(size_t)b * GD + 2 * FD + c] = mn;
    }
}

// ---------------- fc1 (relu) ----------------
__global__ void head1_v13(const float* __restrict__ fc1_b) {
    const int b = blockIdx.x;
    const int o = threadIdx.x;
    __shared__ float sg[GD];
    for (int k = o; k < GD; k += 256) sg[k] = s_G[(size_t)b * GD + k];
    __syncthreads();
    float acc = fc1_b[o];
    #pragma unroll 4
    for (int k = 0; k < GD; ++k) acc = fmaf(sg[k], s_fc1Wt[(size_t)k * Hh + o], acc);
    s_H2[b * Hh + o] = fmaxf(acc, 0.0f);
}

// ---------------- fc2 ----------------
__global__ void head2_v13(const float* __restrict__ fc2_W, const float* __restrict__ fc2_b,
                          float* __restrict__ out) {
    const int b = blockIdx.x;
    const int j = threadIdx.x;
    __shared__ float red[256];
    red[j] = s_H2[b * Hh + j] * fc2_W[j];
    __syncthreads();
    for (int s = 128; s > 0; s >>= 1) {
        if (j < s) red[j] += red[j + s];
        __syncthreads();
    }
    if (j == 0) out[b] = red[0] + fc2_b[0];
}

// ---------------- launch ----------------
extern "C" void kernel_launch(void* const* d_in, const int* in_sizes, int n_in,
                              void* d_out, int out_size) {
    const float* x1     = (const float*)d_in[0];
    const float* states = (const float*)d_in[1];
    const int*   perm1r = (const int*)d_in[2];
    const int*   perm2r = (const int*)d_in[3];
    const float* g2Wih  = (const float*)d_in[4];
    const float* g2Whh  = (const float*)d_in[5];
    const float* g2bih  = (const float*)d_in[6];
    const float* g2bhh  = (const float*)d_in[7];
    const float* g1Wih  = (const float*)d_in[8];
    const float* g1Whh  = (const float*)d_in[9];
    const float* g1bih  = (const float*)d_in[10];
    const float* g1bhh  = (const float*)d_in[11];
    const float* fc1W   = (const float*)d_in[12];
    const float* fc1b   = (const float*)d_in[13];
    const float* fc2W   = (const float*)d_in[14];
    const float* fc2b   = (const float*)d_in[15];
    float* out = (float*)d_out;

    float *whh1T, *fc1Wt, *xw1, *Fbuf, *Pbuf;
    cudaGetSymbolAddress((void**)&whh1T, s_Whh1T);
    cudaGetSymbolAddress((void**)&fc1Wt, s_fc1Wt);
    cudaGetSymbolAddress((void**)&xw1,   s_XW1);
    cudaGetSymbolAddress((void**)&Fbuf,  s_F);
    cudaGetSymbolAddress((void**)&Pbuf,  s_P);

    const int RNN2D_SMEM = (256 * 36 + 32 * TH + 32 * 64) * 4;   // 143360
    cudaFuncSetAttribute(rnn2d_v13, cudaFuncAttributeMaxDynamicSharedMemorySize, RNN2D_SMEM);

    // 1
    wpack_v13<<<(Hh * Hh + 255) / 256, 256>>>(g2Whh);
    // 2: P = states @ g2Wih^T + g2bih   (M=131072, N=768, K=64)
    {
        dim3 g(TH / 64, (Bb * Nn * Mm) / 128);
        mm128_v13<<<g, dim3(16, 16)>>>(states, g2Wih, g2bih, Pbuf, Cc, TH);
    }
    // 3
    perm_conv_v13<<<2, 256>>>(perm1r, perm2r);
    // 4 — ncu target (-s 5 -c 1; 2 harness launches precede ours)
    rnn2d_v13<<<128, 256, RNN2D_SMEM>>>(g2bhh);
    // 5
    stats_v13<<<Bb * Nn, 64>>>(states, x1);
    // 6
    tr_v13<<<(TH * Hh + 255) / 256, 256>>>(g1Whh, whh1T, TH, Hh);
    // 7: XW1 = F @ g1Wih^T + g1bih   (M=2048, N=768, K=912)
    {
        dim3 g(TH / 64, (Bb * Nn) / 128);
        mm128_v13<<<g, dim3(16, 16)>>>(Fbuf, g1Wih, g1bih, xw1, FD, TH);
    }
    // 8
    rnn1d_v13<<<Bb, Hh>>>(g1bhh);
    // 9
    gpool_v13<<<Bb, 256>>>();
    // 10
    tr_v13<<<(Hh * GD + 255) / 256, 256>>>(fc1W, fc1Wt, Hh, GD);
    // 11
    head1_v13<<<Bb, Hh>>>(fc1b);
    // 12
    head2_v13<<<Bb, 256>>>(fc2W, fc2b, out);
}

// round 15
// speedup vs baseline: 1.3532x; 1.3532x over previous
#include <cuda_runtime.h>
#include <cstdint>
#include <cfloat>
#include <math.h>

#define Bb 32
#define Nn 64
#define Mm 64
#define Cc 64
#define C1d 16
#define Hh 256
#define TH 768
#define FD 912
#define GD 2992

// ---------------- device scratch ----------------
__device__ float g_P[(size_t)Bb * Nn * Mm * TH];   // input proj of every states row [131072][768]
__device__ float g_F[(size_t)Bb * Nn * FD];        // f [2048][912]
__device__ float g_XW1[(size_t)Bb * Nn * TH];      // gru1d input proj [2048][768]
__device__ float g_WhhT2[Hh * TH];                 // [256][768]
__device__ float g_Whh1T[Hh * TH];                 // [256][768]
__device__ float g_fc1Wt[GD * Hh];                 // [2992][256]
__device__ float g_G[Bb * GD];
__device__ float g_H2[Bb * Hh];
__device__ int   g_perm1[Nn * Mm];
__device__ int   g_perm2[Nn * Nn];

// ---------------- helpers ----------------
__device__ __forceinline__ float2 unpack2(unsigned long long v) {
    float2 r;
    asm("mov.b64 {%0, %1}, %2;" : "=f"(r.x), "=f"(r.y) : "l"(v));
    return r;
}
__device__ __forceinline__ unsigned long long pack2(float lo, float hi) {
    unsigned long long r;
    asm("mov.b64 %0, {%1, %2};" : "=l"(r) : "f"(lo), "f"(hi));
    return r;
}
__device__ __forceinline__ void ffma2(unsigned long long& d, unsigned long long a, unsigned long long b) {
    asm("fma.rn.f32x2 %0, %1, %2, %0;" : "+l"(d) : "l"(a), "l"(b));
}
__device__ __forceinline__ float tanh_fast(float x) {
    float y; asm("tanh.approx.f32 %0, %1;" : "=f"(y) : "f"(x)); return y;
}
__device__ __forceinline__ float sig_fast(float x) {
    return fmaf(tanh_fast(x * 0.5f), 0.5f, 0.5f);
}
__device__ __forceinline__ void cp_async16(uint32_t dst, const void* src) {
    asm volatile("cp.async.cg.shared.global [%0], [%1], 16;" :: "r"(dst), "l"(src));
}

// ---------------- both perm conversions in one kernel (int64 vs int32 detect) ----------------
__global__ void conv_perm2_kernel(const int* __restrict__ r1, const int* __restrict__ r2) {
    const int* raw = blockIdx.x ? r2 : r1;
    int* out = blockIdx.x ? g_perm2 : g_perm1;
    const int n = Nn * Mm;   // 4096 both
    __shared__ int notI64;
    if (threadIdx.x == 0) notI64 = 0;
    __syncthreads();
    for (int i = threadIdx.x; i < n / 2; i += blockDim.x)
        if (raw[2 * i + 1] != 0) notI64 = 1;
    __syncthreads();
    if (notI64) { for (int i = threadIdx.x; i < n; i += blockDim.x) out[i] = raw[i]; }
    else        { for (int i = threadIdx.x; i < n; i += blockDim.x) out[i] = raw[2 * i]; }
}

// ---------------- transpose in[R][C] -> out[C][R] ----------------
__global__ void transpose_kernel(const float* __restrict__ in, float* __restrict__ out, int R, int C) {
    int idx = blockIdx.x * 256 + threadIdx.x;
    if (idx < R * C) { int r = idx / C, c = idx % C; out[c * R + r] = in[idx]; }
}

// ---------------- stats over states + x1 copy -> F[:, 0:400] ----------------
__global__ void stats_kernel(const float* __restrict__ states, const float* __restrict__ x1) {
    int bi = blockIdx.x;               // b*64 + i
    int b = bi >> 6, i = bi & 63;
    int c = threadIdx.x;               // 64 threads
    float* fr = g_F + (size_t)bi * FD;

    float mx = -FLT_MAX, mn = FLT_MAX, sm = 0.0f;
    for (int n = 0; n < Nn; ++n) {
        float v = states[(((size_t)(b * Nn + n)) * Mm + i) * Cc + c];
        mx = fmaxf(mx, v); mn = fminf(mn, v); sm += v;
    }
    fr[C1d + c]          = mx;
    fr[C1d + Cc + c]     = sm * (1.0f / 64.0f);
    fr[C1d + 2 * Cc + c] = mn;

    mx = -FLT_MAX; mn = FLT_MAX; sm = 0.0f;
    for (int m = 0; m < Mm; ++m) {
        float v = states[(((size_t)(b * Nn + i)) * Mm + m) * Cc + c];
        mx = fmaxf(mx, v); mn = fminf(mn, v); sm += v;
    }
    fr[C1d + 3 * Cc + c] = mx;
    fr[C1d + 4 * Cc + c] = sm * (1.0f / 64.0f);
    fr[C1d + 5 * Cc + c] = mn;

    if (c < C1d) fr[c] = x1[bi * C1d + c];
}

// ---------------- SGEMM 128x64 tile: C[M][N] = A[M][K] @ B[N][K]^T + bias[N] ----------------
__global__ void gemm128_kernel(const float* __restrict__ A, const float* __restrict__ Bm,
                               const float* __restrict__ bias, float* __restrict__ Cm,
                               int K, int Ndim) {
    __shared__ __align__(16) float As[16][132];
    __shared__ __align__(16) float Bs[16][68];
    const int tx = threadIdx.x, ty = threadIdx.y;
    const int tid = ty * 16 + tx;
    const int m0 = blockIdx.y * 128, n0 = blockIdx.x * 64;

    float acc[8][4];
    #pragma unroll
    for (int i = 0; i < 8; ++i)
        #pragma unroll
        for (int jj = 0; jj < 4; ++jj) acc[i][jj] = 0.0f;

    for (int k0 = 0; k0 < K; k0 += 16) {
        #pragma unroll
        for (int e = 0; e < 8; ++e) {
            int idx = tid + e * 256;
            int r = idx >> 4, kk = idx & 15;
            As[kk][r] = A[(size_t)(m0 + r) * K + k0 + kk];
        }
        #pragma unroll
        for (int e = 0; e < 4; ++e) {
            int idx = tid + e * 256;
            int r = idx >> 4, kk = idx & 15;
            Bs[kk][r] = Bm[(size_t)(n0 + r) * K + k0 + kk];
        }
        __syncthreads();
        #pragma unroll
        for (int kk = 0; kk < 16; ++kk) {
            float4 a0 = *reinterpret_cast<const float4*>(&As[kk][ty * 8]);
            float4 a1 = *reinterpret_cast<const float4*>(&As[kk][ty * 8 + 4]);
            float4 b4 = *reinterpret_cast<const float4*>(&Bs[kk][tx * 4]);
            float av[8] = {a0.x, a0.y, a0.z, a0.w, a1.x, a1.y, a1.z, a1.w};
            float bv[4] = {b4.x, b4.y, b4.z, b4.w};
            #pragma unroll
            for (int i = 0; i < 8; ++i)
                #pragma unroll
                for (int jj = 0; jj < 4; ++jj)
                    acc[i][jj] = fmaf(av[i], bv[jj], acc[i][jj]);
        }
        __syncthreads();
    }
    float4 bia = *reinterpret_cast<const float4*>(&bias[n0 + tx * 4]);
    #pragma unroll
    for (int i = 0; i < 8; ++i) {
        float4 v = make_float4(acc[i][0] + bia.x, acc[i][1] + bia.y,
                               acc[i][2] + bia.z, acc[i][3] + bia.w);
        *reinterpret_cast<float4*>(&Cm[(size_t)(m0 + ty * 8 + i) * Ndim + n0 + tx * 4]) = v;
    }
}

// ---------------- persistent 2D GRU: G=32 seqs/CTA, 1 CTA/SM, 128 CTAs (R9 exact) ----------------
// smem: h[256][36] + xw[32][768] + rows[32][64] = 143360 B
__global__ void __launch_bounds__(256)
gru2d_kernel(const float* __restrict__ bhh) {
    const int dir  = blockIdx.x >> 6;           // 0: sd1, 1: sd2
    const int seq0 = (blockIdx.x & 63) * 32;
    const int j    = threadIdx.x;

    extern __shared__ __align__(16) float dyn[];
    float (*sh_h)[36] = (float (*)[36])dyn;              // [256][36]
    float* sh_xw  = dyn + 256 * 36;                      // [32][768]
    int*   sh_row = (int*)(dyn + 256 * 36 + 32 * TH);    // [32][64]

    #pragma unroll
    for (int g = 0; g < 36; ++g) sh_h[j][g] = 0.0f;

    for (int e = j; e < 32 * 64; e += 256) {
        int g = e >> 6, t = e & 63;
        int s = seq0 + g;
        int b = s >> 6, n = s & 63;
        sh_row[e] = (dir == 0)
            ? (b * Nn + n) * Mm + g_perm1[n * Mm + t]
            : (b * Nn + g_perm2[n * Nn + t]) * Mm + n;
    }

    const unsigned long long bR2 = pack2(bhh[j], bhh[j]);
    const unsigned long long bZ2 = pack2(bhh[Hh + j], bhh[Hh + j]);
    const unsigned long long bN2 = pack2(bhh[2 * Hh + j], bhh[2 * Hh + j]);

    const int my_g = j >> 3;                    // 32 rows, 8 threads per row
    const int my_c = j & 7;
    uint32_t xw_dst_base = (uint32_t)__cvta_generic_to_shared(sh_xw + my_g * TH);
    __syncthreads();

    for (int t = 0; t < 64; ++t) {
        // async-gather the 32 precomputed xw rows (32 x 3KB) into smem
        {
            const float* src_row = g_P + (size_t)sh_row[my_g * 64 + t] * TH;
            #pragma unroll
            for (int i = 0; i < 24; ++i) {
                int c16 = my_c + 8 * i;
                cp_async16(xw_dst_base + c16 * 16, src_row + c16 * 4);
            }
            asm volatile("cp.async.commit_group;");
        }

        // ----- recurrent matvec for 16 lane-pairs (32 seqs) -----
        unsigned long long accR[16], accZ[16], ghN[16];
        #pragma unroll
        for (int g = 0; g < 16; ++g) { accR[g] = bR2; accZ[g] = bZ2; ghN[g] = bN2; }

        const float* wph = g_WhhT2 + j;
        #pragma unroll 4
        for (int k = 0; k < Hh; ++k) {
            float wr = wph[k * TH], wz = wph[k * TH + Hh], wn = wph[k * TH + 2 * Hh];
            unsigned long long wr2 = pack2(wr, wr), wz2 = pack2(wz, wz), wn2 = pack2(wn, wn);
            const ulonglong2* hrow = reinterpret_cast<const ulonglong2*>(&sh_h[k][0]);
            #pragma unroll
            for (int q = 0; q < 8; ++q) {
                ulonglong2 hp = hrow[q];       // pairs 2q, 2q+1
                ffma2(accR[2 * q],     wr2, hp.x);
                ffma2(accZ[2 * q],     wz2, hp.x);
                ffma2(ghN[2 * q],      wn2, hp.x);
                ffma2(accR[2 * q + 1], wr2, hp.y);
                ffma2(accZ[2 * q + 1], wz2, hp.y);
                ffma2(ghN[2 * q + 1],  wn2, hp.y);
            }
        }

        asm volatile("cp.async.wait_group 0;" ::: "memory");
        __syncthreads();

        float hnew[32];
        #pragma unroll
        for (int gg = 0; gg < 16; ++gg) {
            const float* x0 = sh_xw + (2 * gg) * TH + j;
            const float* x1 = sh_xw + (2 * gg + 1) * TH + j;
            float2 aR = unpack2(accR[gg]);
            float2 aZ = unpack2(accZ[gg]);
            float2 hN = unpack2(ghN[gg]);
            float r0 = sig_fast(aR.x + x0[0]);
            float z0 = sig_fast(aZ.x + x0[Hh]);
            float n0 = tanh_fast(x0[2 * Hh] + r0 * hN.x);
            hnew[2 * gg]     = (1.0f - z0) * n0 + z0 * sh_h[j][2 * gg];
            float r1 = sig_fast(aR.y + x1[0]);
            float z1 = sig_fast(aZ.y + x1[Hh]);
            float n1 = tanh_fast(x1[2 * Hh] + r1 * hN.y);
            hnew[2 * gg + 1] = (1.0f - z1) * n1 + z1 * sh_h[j][2 * gg + 1];
        }
        __syncthreads();
        #pragma unroll
        for (int g = 0; g < 32; ++g) sh_h[j][g] = hnew[g];
        __syncthreads();
    }

    const int off = (dir == 0) ? (C1d + 6 * Cc) : (C1d + 6 * Cc + Hh);  // 400 / 656
    #pragma unroll
    for (int g = 0; g < 32; ++g)
        g_F[(size_t)(seq0 + g) * FD + off + j] = sh_h[j][g];
}

// ---------------- 1D GRU: 32 blocks x 256 threads, float4 weight rows ----------------
__global__ void gru1d_kernel(const float* __restrict__ bhh) {
    const int b = blockIdx.x;
    const int tid = threadIdx.x;
    __shared__ float sh_h[Hh];
    __shared__ float sums[TH];
    sh_h[tid] = 0.0f;
    const float br = bhh[tid], bz = bhh[Hh + tid], bn = bhh[2 * Hh + tid];
    __syncthreads();

    for (int t = 0; t < 64; ++t) {
        if (tid < 192) {
            float4 acc = make_float4(0.0f, 0.0f, 0.0f, 0.0f);
            const float* wbase = g_Whh1T + 4 * tid;
            #pragma unroll 8
            for (int k = 0; k < Hh; ++k) {
                float4 w = *reinterpret_cast<const float4*>(wbase + k * TH);
                float hv = sh_h[k];
                acc.x = fmaf(w.x, hv, acc.x);
                acc.y = fmaf(w.y, hv, acc.y);
                acc.z = fmaf(w.z, hv, acc.z);
                acc.w = fmaf(w.w, hv, acc.w);
            }
            *reinterpret_cast<float4*>(&sums[4 * tid]) = acc;
        }
        __syncthreads();

        const float* xw = g_XW1 + (size_t)(b * 64 + t) * TH;  // includes bih
        float r = sig_fast(xw[tid] + sums[tid] + br);
        float z = sig_fast(xw[Hh + tid] + sums[Hh + tid] + bz);
        float n = tanh_fast(xw[2 * Hh + tid] + r * (sums[2 * Hh + tid] + bn));
        float hnew = (1.0f - z) * n + z * sh_h[tid];
        __syncthreads();
        sh_h[tid] = hnew;
        __syncthreads();
    }
    g_G[(size_t)b * GD + 3 * FD + tid] = sh_h[tid];
}

// ---------------- g = [f.max(1), f.mean(1), f.min(1)] -> G[:, 0:2736] ----------------
__global__ void finalg_kernel() {
    const int b = blockIdx.x;
    for (int c = threadIdx.x; c < FD; c += 256) {
        float mx = -FLT_MAX, mn = FLT_MAX, sm = 0.0f;
        for (int n = 0; n < Nn; ++n) {
            float v = g_F[(size_t)(b * Nn + n) * FD + c];
            mx = fmaxf(mx, v); mn = fminf(mn, v); sm += v;
        }
        g_G[(size_t)b * GD + c]          = mx;
        g_G[(size_t)b * GD + FD + c]     = sm * (1.0f / 64.0f);
        g_G[(size_t)b * GD + 2 * FD + c] = mn;
    }
}

// ---------------- fc1 (relu) ----------------
__global__ void fc1_kernel(const float* __restrict__ fc1_b) {
    const int b = blockIdx.x;
    const int o = threadIdx.x;
    __shared__ float sg[GD];
    for (int k = o; k < GD; k += 256) sg[k] = g_G[(size_t)b * GD + k];
    __syncthreads();
    float acc = fc1_b[o];
    #pragma unroll 4
    for (int k = 0; k < GD; ++k) acc = fmaf(sg[k], g_fc1Wt[(size_t)k * Hh + o], acc);
    g_H2[b * Hh + o] = fmaxf(acc, 0.0f);
}

// ---------------- fc2 ----------------
__global__ void fc2_kernel(const float* __restrict__ fc2_W, const float* __restrict__ fc2_b,
                           float* __restrict__ out) {
    const int b = blockIdx.x;
    const int j = threadIdx.x;
    __shared__ float red[256];
    red[j] = g_H2[b * Hh + j] * fc2_W[j];
    __syncthreads();
    for (int s = 128; s > 0; s >>= 1) {
        if (j < s) red[j] += red[j + s];
        __syncthreads();
    }
    if (j == 0) out[b] = red[0] + fc2_b[0];
}

// ---------------- launch ----------------
extern "C" void kernel_launch(void* const* d_in, const int* in_sizes, int n_in,
                              void* d_out, int out_size) {
    const float* x1     = (const float*)d_in[0];
    const float* states = (const float*)d_in[1];
    const int*   perm1r = (const int*)d_in[2];
    const int*   perm2r = (const int*)d_in[3];
    const float* g2Wih  = (const float*)d_in[4];
    const float* g2Whh  = (const float*)d_in[5];
    const float* g2bih  = (const float*)d_in[6];
    const float* g2bhh  = (const float*)d_in[7];
    const float* g1Wih  = (const float*)d_in[8];
    const float* g1Whh  = (const float*)d_in[9];
    const float* g1bih  = (const float*)d_in[10];
    const float* g1bhh  = (const float*)d_in[11];
    const float* fc1W   = (const float*)d_in[12];
    const float* fc1b   = (const float*)d_in[13];
    const float* fc2W   = (const float*)d_in[14];
    const float* fc2b   = (const float*)d_in[15];
    float* out = (float*)d_out;

    float *whhT2, *whh1T, *fc1Wt, *xw1, *Fbuf, *Pbuf;
    cudaGetSymbolAddress((void**)&whhT2, g_WhhT2);
    cudaGetSymbolAddress((void**)&whh1T, g_Whh1T);
    cudaGetSymbolAddress((void**)&fc1Wt, g_fc1Wt);
    cudaGetSymbolAddress((void**)&xw1,   g_XW1);
    cudaGetSymbolAddress((void**)&Fbuf,  g_F);
    cudaGetSymbolAddress((void**)&Pbuf,  g_P);

    const int GRU2D_SMEM = (256 * 36 + 32 * TH + 32 * 64) * 4;   // 143360
    cudaFuncSetAttribute(gru2d_kernel, cudaFuncAttributeMaxDynamicSharedMemorySize, GRU2D_SMEM);

    // 1
    transpose_kernel<<<(TH * Hh + 255) / 256, 256>>>(g2Whh, whhT2, TH, Hh);
    // 2: P = states @ g2Wih^T + g2bih   (M=131072, N=768, K=64)
    {
        dim3 g(TH / 64, (Bb * Nn * Mm) / 128);
        gemm128_kernel<<<g, dim3(16, 16)>>>(states, g2Wih, g2bih, Pbuf, Cc, TH);
    }
    // 3
    conv_perm2_kernel<<<2, 256>>>(perm1r, perm2r);
    // 4 — ncu target (-s 5 -c 1; 2 harness launches precede ours)
    gru2d_kernel<<<128, 256, GRU2D_SMEM>>>(g2bhh);
    // 5
    stats_kernel<<<Bb * Nn, 64>>>(states, x1);
    // 6
    transpose_kernel<<<(TH * Hh + 255) / 256, 256>>>(g1Whh, whh1T, TH, Hh);
    // 7: XW1 = F @ g1Wih^T + g1bih   (M=2048, N=768, K=912)
    {
        dim3 g(TH / 64, (Bb * Nn) / 128);
        gemm128_kernel<<<g, dim3(16, 16)>>>(Fbuf, g1Wih, g1bih, xw1, FD, TH);
    }
    // 8
    gru1d_kernel<<<Bb, Hh>>>(g1bhh);
    // 9
    finalg_kernel<<<Bb, 256>>>();
    // 10
    transpose_kernel<<<(Hh * GD + 255) / 256, 256>>>(fc1W, fc1Wt, Hh, GD);
    // 11
    fc1_kernel<<<Bb, Hh>>>(fc1b);
    // 12
    fc2_kernel<<<Bb, 256>>>(fc2W, fc2b, out);
}

// round 16
// speedup vs baseline: 1.8044x; 1.3334x over previous
#include <cuda_runtime.h>
#include <cstdint>
#include <cfloat>
#include <math.h>

#define Bb 32
#define Nn 64
#define Mm 64
#define Cc 64
#define C1d 16
#define Hh 256
#define TH 768
#define FD 912
#define GD 2992

// ---------------- device scratch ----------------
__device__ float g_P[(size_t)Bb * Nn * Mm * TH];   // input proj of every states row [131072][768]
__device__ float g_F[(size_t)Bb * Nn * FD];        // f [2048][912]
__device__ float g_XW1[(size_t)Bb * Nn * TH];      // gru1d input proj [2048][768]
__device__ float g_WhhT2[Hh * TH];                 // [256][768]
__device__ float g_Whh1T[Hh * TH];                 // [256][768]
__device__ float g_fc1Wt[GD * Hh];                 // [2992][256]
__device__ float g_G[Bb * GD];
__device__ float g_H2[Bb * Hh];
__device__ int   g_perm1[Nn * Mm];
__device__ int   g_perm2[Nn * Nn];

// ---------------- helpers ----------------
__device__ __forceinline__ unsigned long long pack2(float lo, float hi) {
    unsigned long long r;
    asm("mov.b64 %0, {%1, %2};" : "=l"(r) : "f"(lo), "f"(hi));
    return r;
}
__device__ __forceinline__ float2 unpack2(unsigned long long v) {
    float2 r;
    asm("mov.b64 {%0, %1}, %2;" : "=f"(r.x), "=f"(r.y) : "l"(v));
    return r;
}
__device__ __forceinline__ void ffma2(unsigned long long& d, unsigned long long a, unsigned long long b) {
    asm("fma.rn.f32x2 %0, %1, %2, %0;" : "+l"(d) : "l"(a), "l"(b));
}
__device__ __forceinline__ float tanh_fast(float x) {
    float y; asm("tanh.approx.f32 %0, %1;" : "=f"(y) : "f"(x)); return y;
}
__device__ __forceinline__ float sig_fast(float x) {
    return fmaf(tanh_fast(x * 0.5f), 0.5f, 0.5f);
}
__device__ __forceinline__ void cp_async16(uint32_t dst, const void* src) {
    asm volatile("cp.async.cg.shared.global [%0], [%1], 16;" :: "r"(dst), "l"(src));
}

// ---------------- both perm conversions in one kernel (int64 vs int32 detect) ----------------
__global__ void conv_perm2_kernel(const int* __restrict__ r1, const int* __restrict__ r2) {
    const int* raw = blockIdx.x ? r2 : r1;
    int* out = blockIdx.x ? g_perm2 : g_perm1;
    const int n = Nn * Mm;   // 4096 both
    __shared__ int notI64;
    if (threadIdx.x == 0) notI64 = 0;
    __syncthreads();
    for (int i = threadIdx.x; i < n / 2; i += blockDim.x)
        if (raw[2 * i + 1] != 0) notI64 = 1;
    __syncthreads();
    if (notI64) { for (int i = threadIdx.x; i < n; i += blockDim.x) out[i] = raw[i]; }
    else        { for (int i = threadIdx.x; i < n; i += blockDim.x) out[i] = raw[2 * i]; }
}

// ---------------- transpose in[R][C] -> out[C][R] ----------------
__global__ void transpose_kernel(const float* __restrict__ in, float* __restrict__ out, int R, int C) {
    int idx = blockIdx.x * 256 + threadIdx.x;
    if (idx < R * C) { int r = idx / C, c = idx % C; out[c * R + r] = in[idx]; }
}

// ---------------- stats over states + x1 copy -> F[:, 0:400] ----------------
__global__ void stats_kernel(const float* __restrict__ states, const float* __restrict__ x1) {
    int bi = blockIdx.x;               // b*64 + i
    int b = bi >> 6, i = bi & 63;
    int c = threadIdx.x;               // 64 threads
    float* fr = g_F + (size_t)bi * FD;

    float mx = -FLT_MAX, mn = FLT_MAX, sm = 0.0f;
    for (int n = 0; n < Nn; ++n) {
        float v = states[(((size_t)(b * Nn + n)) * Mm + i) * Cc + c];
        mx = fmaxf(mx, v); mn = fminf(mn, v); sm += v;
    }
    fr[C1d + c]          = mx;
    fr[C1d + Cc + c]     = sm * (1.0f / 64.0f);
    fr[C1d + 2 * Cc + c] = mn;

    mx = -FLT_MAX; mn = FLT_MAX; sm = 0.0f;
    for (int m = 0; m < Mm; ++m) {
        float v = states[(((size_t)(b * Nn + i)) * Mm + m) * Cc + c];
        mx = fmaxf(mx, v); mn = fminf(mn, v); sm += v;
    }
    fr[C1d + 3 * Cc + c] = mx;
    fr[C1d + 4 * Cc + c] = sm * (1.0f / 64.0f);
    fr[C1d + 5 * Cc + c] = mn;

    if (c < C1d) fr[c] = x1[bi * C1d + c];
}

// ---------------- SGEMM 128x64 tile: C[M][N] = A[M][K] @ B[N][K]^T + bias[N] ----------------
__global__ void gemm128_kernel(const float* __restrict__ A, const float* __restrict__ Bm,
                               const float* __restrict__ bias, float* __restrict__ Cm,
                               int K, int Ndim) {
    __shared__ __align__(16) float As[16][132];
    __shared__ __align__(16) float Bs[16][68];
    const int tx = threadIdx.x, ty = threadIdx.y;
    const int tid = ty * 16 + tx;
    const int m0 = blockIdx.y * 128, n0 = blockIdx.x * 64;

    float acc[8][4];
    #pragma unroll
    for (int i = 0; i < 8; ++i)
        #pragma unroll
        for (int jj = 0; jj < 4; ++jj) acc[i][jj] = 0.0f;

    for (int k0 = 0; k0 < K; k0 += 16) {
        #pragma unroll
        for (int e = 0; e < 8; ++e) {
            int idx = tid + e * 256;
            int r = idx >> 4, kk = idx & 15;
            As[kk][r] = A[(size_t)(m0 + r) * K + k0 + kk];
        }
        #pragma unroll
        for (int e = 0; e < 4; ++e) {
            int idx = tid + e * 256;
            int r = idx >> 4, kk = idx & 15;
            Bs[kk][r] = Bm[(size_t)(n0 + r) * K + k0 + kk];
        }
        __syncthreads();
        #pragma unroll
        for (int kk = 0; kk < 16; ++kk) {
            float4 a0 = *reinterpret_cast<const float4*>(&As[kk][ty * 8]);
            float4 a1 = *reinterpret_cast<const float4*>(&As[kk][ty * 8 + 4]);
            float4 b4 = *reinterpret_cast<const float4*>(&Bs[kk][tx * 4]);
            float av[8] = {a0.x, a0.y, a0.z, a0.w, a1.x, a1.y, a1.z, a1.w};
            float bv[4] = {b4.x, b4.y, b4.z, b4.w};
            #pragma unroll
            for (int i = 0; i < 8; ++i)
                #pragma unroll
                for (int jj = 0; jj < 4; ++jj)
                    acc[i][jj] = fmaf(av[i], bv[jj], acc[i][jj]);
        }
        __syncthreads();
    }
    float4 bia = *reinterpret_cast<const float4*>(&bias[n0 + tx * 4]);
    #pragma unroll
    for (int i = 0; i < 8; ++i) {
        float4 v = make_float4(acc[i][0] + bia.x, acc[i][1] + bia.y,
                               acc[i][2] + bia.z, acc[i][3] + bia.w);
        *reinterpret_cast<float4*>(&Cm[(size_t)(m0 + ty * 8 + i) * Ndim + n0 + tx * 4]) = v;
    }
}

// ---------------- persistent 2D GRU: G=32 seqs/CTA, 1 CTA/SM, 128 CTAs ----------------
// smem: h[256][36] + xw[32][768] + rows[32][64] = 143360 B
__global__ void __launch_bounds__(256, 1)
gru2d_kernel(const float* __restrict__ bhh) {
    const int dir  = blockIdx.x >> 6;           // 0: sd1, 1: sd2
    const int seq0 = (blockIdx.x & 63) * 32;    // seq within dir, 0..2047
    const int j    = threadIdx.x;

    extern __shared__ __align__(16) float dyn[];
    float (*sh_h)[36] = (float (*)[36])dyn;              // [256][36]
    float* sh_xw  = dyn + 256 * 36;                      // [32][768]
    int*   sh_row = (int*)(dyn + 256 * 36 + 32 * TH);    // [32][64]

    #pragma unroll
    for (int g = 0; g < 36; ++g) sh_h[j][g] = 0.0f;

    // precompute all gather row indices
    for (int e = j; e < 32 * 64; e += 256) {
        int g = e >> 6, t = e & 63;
        int s = seq0 + g;                      // 0..2047
        int b = s >> 6, n = s & 63;
        sh_row[e] = (dir == 0)
            ? (b * Nn + n) * Mm + g_perm1[n * Mm + t]
            : (b * Nn + g_perm2[n * Nn + t]) * Mm + n;
    }

    const float bhhr = bhh[j], bhhz = bhh[Hh + j], bhhn = bhh[2 * Hh + j];
    const unsigned long long bR2 = pack2(bhhr, bhhr);
    const unsigned long long bZ2 = pack2(bhhz, bhhz);
    const unsigned long long bN2 = pack2(bhhn, bhhn);

    const int my_g  = j >> 3;                  // 32 rows, 8 threads per row
    const int my_c  = j & 7;
    uint32_t xw_dst_base = (uint32_t)__cvta_generic_to_shared(sh_xw + my_g * TH);
    __syncthreads();

    for (int t = 0; t < 64; ++t) {
        // async-gather the 32 precomputed xw rows (32 x 3KB) into smem
        {
            const float* src_row = g_P + (size_t)sh_row[my_g * 64 + t] * TH;
            #pragma unroll
            for (int i = 0; i < 24; ++i) {
                int c16 = my_c + 8 * i;        // 0..191 (16B chunks)
                cp_async16(xw_dst_base + c16 * 16, src_row + c16 * 4);
            }
            asm volatile("cp.async.commit_group;");
        }

        // ----- recurrent matvec for 16 lane-pairs (32 seqs) -----
        unsigned long long accR[16], accZ[16], ghN[16];
        #pragma unroll
        for (int g = 0; g < 16; ++g) { accR[g] = bR2; accZ[g] = bZ2; ghN[g] = bN2; }

        const float* wph = g_WhhT2 + j;
        #pragma unroll 4
        for (int k = 0; k < Hh; ++k) {
            float wr = wph[k * TH], wz = wph[k * TH + Hh], wn = wph[k * TH + 2 * Hh];
            unsigned long long wr2 = pack2(wr, wr), wz2 = pack2(wz, wz), wn2 = pack2(wn, wn);
            const ulonglong2* hrow = reinterpret_cast<const ulonglong2*>(&sh_h[k][0]);
            #pragma unroll
            for (int q = 0; q < 8; ++q) {
                ulonglong2 hp = hrow[q];       // pairs 2q, 2q+1
                ffma2(accR[2 * q],     wr2, hp.x);
                ffma2(accZ[2 * q],     wz2, hp.x);
                ffma2(ghN[2 * q],      wn2, hp.x);
                ffma2(accR[2 * q + 1], wr2, hp.y);
                ffma2(accZ[2 * q + 1], wz2, hp.y);
                ffma2(ghN[2 * q + 1],  wn2, hp.y);
            }
        }

        asm volatile("cp.async.wait_group 0;" ::: "memory");
        __syncthreads();

        float hnew[32];
        #pragma unroll
        for (int gg = 0; gg < 16; ++gg) {
            const float* x0 = sh_xw + (2 * gg) * TH + j;
            const float* x1 = sh_xw + (2 * gg + 1) * TH + j;
            float2 aR = unpack2(accR[gg]);
            float2 aZ = unpack2(accZ[gg]);
            float2 hN = unpack2(ghN[gg]);
            float r0 = sig_fast(aR.x + x0[0]);
            float z0 = sig_fast(aZ.x + x0[Hh]);
            float n0 = tanh_fast(x0[2 * Hh] + r0 * hN.x);
            hnew[2 * gg]     = (1.0f - z0) * n0 + z0 * sh_h[j][2 * gg];
            float r1 = sig_fast(aR.y + x1[0]);
            float z1 = sig_fast(aZ.y + x1[Hh]);
            float n1 = tanh_fast(x1[2 * Hh] + r1 * hN.y);
            hnew[2 * gg + 1] = (1.0f - z1) * n1 + z1 * sh_h[j][2 * gg + 1];
        }
        __syncthreads();
        #pragma unroll
        for (int g = 0; g < 32; ++g) sh_h[j][g] = hnew[g];
        __syncthreads();
    }

    const int off = (dir == 0) ? (C1d + 6 * Cc) : (C1d + 6 * Cc + Hh);  // 400 / 656
    #pragma unroll
    for (int g = 0; g < 32; ++g)
        g_F[(size_t)(seq0 + g) * FD + off + j] = sh_h[j][g];
}

// ---------------- 1D GRU: 32 blocks x 256 threads, float4 weight rows ----------------
__global__ void gru1d_kernel(const float* __restrict__ bhh) {
    const int b = blockIdx.x;
    const int tid = threadIdx.x;
    __shared__ float sh_h[Hh];
    __shared__ float sums[TH];
    sh_h[tid] = 0.0f;
    const float br = bhh[tid], bz = bhh[Hh + tid], bn = bhh[2 * Hh + tid];
    __syncthreads();

    for (int t = 0; t < 64; ++t) {
        if (tid < 192) {
            float4 acc = make_float4(0.0f, 0.0f, 0.0f, 0.0f);
            const float* wbase = g_Whh1T + 4 * tid;
            #pragma unroll 8
            for (int k = 0; k < Hh; ++k) {
                float4 w = *reinterpret_cast<const float4*>(wbase + k * TH);
                float hv = sh_h[k];
                acc.x = fmaf(w.x, hv, acc.x);
                acc.y = fmaf(w.y, hv, acc.y);
                acc.z = fmaf(w.z, hv, acc.z);
                acc.w = fmaf(w.w, hv, acc.w);
            }
            *reinterpret_cast<float4*>(&sums[4 * tid]) = acc;
        }
        __syncthreads();

        const float* xw = g_XW1 + (size_t)(b * 64 + t) * TH;  // includes bih
        float r = sig_fast(xw[tid] + sums[tid] + br);
        float z = sig_fast(xw[Hh + tid] + sums[Hh + tid] + bz);
        float n = tanh_fast(xw[2 * Hh + tid] + r * (sums[2 * Hh + tid] + bn));
        float hnew = (1.0f - z) * n + z * sh_h[tid];
        __syncthreads();
        sh_h[tid] = hnew;
        __syncthreads();
    }
    g_G[(size_t)b * GD + 3 * FD + tid] = sh_h[tid];
}

// ---------------- g = [f.max(1), f.mean(1), f.min(1)] -> G[:, 0:2736] ----------------
__global__ void finalg_kernel() {
    const int b = blockIdx.x;
    for (int c = threadIdx.x; c < FD; c += 256) {
        float mx = -FLT_MAX, mn = FLT_MAX, sm = 0.0f;
        for (int n = 0; n < Nn; ++n) {
            float v = g_F[(size_t)(b * Nn + n) * FD + c];
            mx = fmaxf(mx, v); mn = fminf(mn, v); sm += v;
        }
        g_G[(size_t)b * GD + c]          = mx;
        g_G[(size_t)b * GD + FD + c]     = sm * (1.0f / 64.0f);
        g_G[(size_t)b * GD + 2 * FD + c] = mn;
    }
}

// ---------------- fc1 (relu) ----------------
__global__ void fc1_kernel(const float* __restrict__ fc1_b) {
    const int b = blockIdx.x;
    const int o = threadIdx.x;
    __shared__ float sg[GD];
    for (int k = o; k < GD; k += 256) sg[k] = g_G[(size_t)b * GD + k];
    __syncthreads();
    float acc = fc1_b[o];
    #pragma unroll 4
    for (int k = 0; k < GD; ++k) acc = fmaf(sg[k], g_fc1Wt[(size_t)k * Hh + o], acc);
    g_H2[b * Hh + o] = fmaxf(acc, 0.0f);
}

// ---------------- fc2 ----------------
__global__ void fc2_kernel(const float* __restrict__ fc2_W, const float* __restrict__ fc2_b,
                           float* __restrict__ out) {
    const int b = blockIdx.x;
    const int j = threadIdx.x;
    __shared__ float red[256];
    red[j] = g_H2[b * Hh + j] * fc2_W[j];
    __syncthreads();
    for (int s = 128; s > 0; s >>= 1) {
        if (j < s) red[j] += red[j + s];
        __syncthreads();
    }
    if (j == 0) out[b] = red[0] + fc2_b[0];
}

// ---------------- launch ----------------
extern "C" void kernel_launch(void* const* d_in, const int* in_sizes, int n_in,
                              void* d_out, int out_size) {
    const float* x1     = (const float*)d_in[0];
    const float* states = (const float*)d_in[1];
    const int*   perm1r = (const int*)d_in[2];
    const int*   perm2r = (const int*)d_in[3];
    const float* g2Wih  = (const float*)d_in[4];
    const float* g2Whh  = (const float*)d_in[5];
    const float* g2bih  = (const float*)d_in[6];
    const float* g2bhh  = (const float*)d_in[7];
    const float* g1Wih  = (const float*)d_in[8];
    const float* g1Whh  = (const float*)d_in[9];
    const float* g1bih  = (const float*)d_in[10];
    const float* g1bhh  = (const float*)d_in[11];
    const float* fc1W   = (const float*)d_in[12];
    const float* fc1b   = (const float*)d_in[13];
    const float* fc2W   = (const float*)d_in[14];
    const float* fc2b   = (const float*)d_in[15];
    float* out = (float*)d_out;

    float *whhT2, *whh1T, *fc1Wt, *xw1, *Fbuf, *Pbuf;
    cudaGetSymbolAddress((void**)&whhT2, g_WhhT2);
    cudaGetSymbolAddress((void**)&whh1T, g_Whh1T);
    cudaGetSymbolAddress((void**)&fc1Wt, g_fc1Wt);
    cudaGetSymbolAddress((void**)&xw1,   g_XW1);
    cudaGetSymbolAddress((void**)&Fbuf,  g_F);
    cudaGetSymbolAddress((void**)&Pbuf,  g_P);

    const int GRU2D_SMEM = (256 * 36 + 32 * TH + 32 * 64) * 4;   // 143360
    cudaFuncSetAttribute(gru2d_kernel, cudaFuncAttributeMaxDynamicSharedMemorySize, GRU2D_SMEM);

    // 1
    transpose_kernel<<<(TH * Hh + 255) / 256, 256>>>(g2Whh, whhT2, TH, Hh);
    // 2: P = states @ g2Wih^T + g2bih   (M=131072, N=768, K=64)
    {
        dim3 g(TH / 64, (Bb * Nn * Mm) / 128);
        gemm128_kernel<<<g, dim3(16, 16)>>>(states, g2Wih, g2bih, Pbuf, Cc, TH);
    }
    // 3
    conv_perm2_kernel<<<2, 256>>>(perm1r, perm2r);
    // 4 — ncu target (-s 5 -c 1; 2 harness launches precede ours)
    gru2d_kernel<<<128, 256, GRU2D_SMEM>>>(g2bhh);
    // 5
    stats_kernel<<<Bb * Nn, 64>>>(states, x1);
    // 6
    transpose_kernel<<<(TH * Hh + 255) / 256, 256>>>(g1Whh, whh1T, TH, Hh);
    // 7: XW1 = F @ g1Wih^T + g1bih   (M=2048, N=768, K=912)
    {
        dim3 g(TH / 64, (Bb * Nn) / 128);
        gemm128_kernel<<<g, dim3(16, 16)>>>(Fbuf, g1Wih, g1bih, xw1, FD, TH);
    }
    // 8
    gru1d_kernel<<<Bb, Hh>>>(g1bhh);
    // 9
    finalg_kernel<<<Bb, 256>>>();
    // 10
    transpose_kernel<<<(Hh * GD + 255) / 256, 256>>>(fc1W, fc1Wt, Hh, GD);
    // 11
    fc1_kernel<<<Bb, Hh>>>(fc1b);
    // 12
    fc2_kernel<<<Bb, 256>>>(fc2W, fc2b, out);
}